// round 13
// baseline (speedup 1.0000x reference)
#include <cuda_runtime.h>
#include <cuda_bf16.h>

// Problem constants
#define B_ROWS   65536
#define FDIM     512
#define WARPS_PER_BLOCK 8
#define THREADS_PER_BLOCK (WARPS_PER_BLOCK * 32)
#define BLOCKS_PER_SM 6
#define NUM_BLOCKS (148 * BLOCKS_PER_SM)            // 888 persistent blocks
#define TOTAL_WARPS (NUM_BLOCKS * WARPS_PER_BLOCK)  // 7104
#define MAX_T 10                                    // ceil(65536/7104)

// Deterministic reduction scratch (no allocation allowed)
__device__ float g_partial[NUM_BLOCKS];
__device__ unsigned int g_count;   // zero-init; last block resets to 0 each replay

__device__ __forceinline__ float row_dot_single(const float4* __restrict__ in4,
                                                const float4* __restrict__ c4,
                                                int lane)
{
    float acc = 0.0f;
#pragma unroll
    for (int i = 0; i < 4; i++) {
        float4 a = __ldcs(&in4[lane + i * 32]);
        float4 c = __ldg(&c4[lane + i * 32]);
        acc = fmaf(a.x, c.x, acc);
        acc = fmaf(a.y, c.y, acc);
        acc = fmaf(a.z, c.z, acc);
        acc = fmaf(a.w, c.w, acc);
    }
#pragma unroll
    for (int off = 16; off > 0; off >>= 1)
        acc += __shfl_xor_sync(0xFFFFFFFFu, acc, off);
    return acc;
}

__global__ __launch_bounds__(THREADS_PER_BLOCK, BLOCKS_PER_SM)
void predict_kernel(const float* __restrict__ input,
                    const float* __restrict__ factor,
                    const int* __restrict__ label,     // int32 (JAX x64 disabled)
                    const float* __restrict__ centers,
                    float* __restrict__ out,           // out[0]=loss, out[1..B]=predict_a
                    int out_size)
{
    __shared__ float s_loss[WARPS_PER_BLOCK];
    __shared__ bool  s_is_last;

    const int warp_in_block = threadIdx.x >> 5;
    const int lane = threadIdx.x & 31;
    const int gwarp = blockIdx.x * WARPS_PER_BLOCK + warp_in_block;

    // ---- Lane-parallel prefetch of per-row scalars (labels + factors) ----
    int   my_label  = 0;
    float my_factor = 0.0f;
    {
        int r = gwarp + lane * TOTAL_WARPS;
        if (lane < MAX_T && r < B_ROWS) {
            my_label  = label[r];
            my_factor = __ldg(&factor[r]);
        }
    }

    float warp_loss = 0.0f;   // lane 0, fixed t-ascending order -> deterministic

    // ---- 4 full pairs: t = (0,1),(2,3),(4,5),(6,7); valid for every warp
    //      (gwarp + 7*7104 = gwarp + 49728 < 65536 always)
#pragma unroll
    for (int m = 0; m < 4; m++) {
        const int t0 = 2 * m, t1 = 2 * m + 1;
        const int rowA = gwarp + t0 * TOTAL_WARPS;
        const int rowB = gwarp + t1 * TOTAL_WARPS;

        const int   labA = __shfl_sync(0xFFFFFFFFu, my_label, t0);
        const float facA = __shfl_sync(0xFFFFFFFFu, my_factor, t0);
        const int   labB = __shfl_sync(0xFFFFFFFFu, my_label, t1);
        const float facB = __shfl_sync(0xFFFFFFFFu, my_factor, t1);

        const float4* __restrict__ inA = reinterpret_cast<const float4*>(input + (size_t)rowA * FDIM);
        const float4* __restrict__ cA  = reinterpret_cast<const float4*>(centers + (size_t)labA * FDIM);
        const float4* __restrict__ inB = reinterpret_cast<const float4*>(input + (size_t)rowB * FDIM);
        const float4* __restrict__ cB  = reinterpret_cast<const float4*>(centers + (size_t)labB * FDIM);

        float acc0 = 0.0f, acc1 = 0.0f;
#pragma unroll
        for (int i = 0; i < 4; i++) {
            float4 a0 = __ldcs(&inA[lane + i * 32]);
            float4 c0 = __ldg(&cA[lane + i * 32]);
            float4 a1 = __ldcs(&inB[lane + i * 32]);
            float4 c1 = __ldg(&cB[lane + i * 32]);
            acc0 = fmaf(a0.x, c0.x, acc0);
            acc1 = fmaf(a1.x, c1.x, acc1);
            acc0 = fmaf(a0.y, c0.y, acc0);
            acc1 = fmaf(a1.y, c1.y, acc1);
            acc0 = fmaf(a0.z, c0.z, acc0);
            acc1 = fmaf(a1.z, c1.z, acc1);
            acc0 = fmaf(a0.w, c0.w, acc0);
            acc1 = fmaf(a1.w, c1.w, acc1);
        }

        // Interleaved warp reduces: two independent chains share the latency
#pragma unroll
        for (int off = 16; off > 0; off >>= 1) {
            acc0 += __shfl_xor_sync(0xFFFFFFFFu, acc0, off);
            acc1 += __shfl_xor_sync(0xFFFFFFFFu, acc1, off);
        }

        if (lane == 0) {
            float pA = 12.0f * tanhf(acc0);
            float pB = 12.0f * tanhf(acc1);
            out[1 + rowA] = pA;
            out[1 + rowB] = pB;
            float dA = pA - facA, dB = pB - facB;
            float adA = fabsf(dA), adB = fabsf(dB);
            warp_loss += (adA < 1.0f) ? 0.5f * dA * dA : (adA - 0.5f);
            warp_loss += (adB < 1.0f) ? 0.5f * dB * dB : (adB - 0.5f);
        }
    }

    // ---- Tail singles: t=8 (always valid), t=9 (only gwarp < 1600)
#pragma unroll
    for (int t = 8; t < MAX_T; t++) {
        const int row = gwarp + t * TOTAL_WARPS;
        if (row >= B_ROWS) break;
        const int   lab = __shfl_sync(0xFFFFFFFFu, my_label, t);
        const float fac = __shfl_sync(0xFFFFFFFFu, my_factor, t);
        const float4* __restrict__ in4 = reinterpret_cast<const float4*>(input + (size_t)row * FDIM);
        const float4* __restrict__ c4  = reinterpret_cast<const float4*>(centers + (size_t)lab * FDIM);
        float acc = row_dot_single(in4, c4, lane);
        if (lane == 0) {
            float p = 12.0f * tanhf(acc);
            out[1 + row] = p;
            float d = p - fac;
            float ad = fabsf(d);
            warp_loss += (ad < 1.0f) ? 0.5f * d * d : (ad - 0.5f);
        }
    }

    if (lane == 0) s_loss[warp_in_block] = warp_loss;
    __syncthreads();

    if (threadIdx.x == 0) {
        float s = 0.0f;
#pragma unroll
        for (int w = 0; w < WARPS_PER_BLOCK; w++) s += s_loss[w];
        g_partial[blockIdx.x] = s;
        __threadfence();
        unsigned int old = atomicAdd(&g_count, 1u);
        s_is_last = (old == NUM_BLOCKS - 1);
    }
    __syncthreads();

    // Last-arriving block reduces all partials in a FIXED order (deterministic).
    if (s_is_last) {
        __shared__ float s_red[THREADS_PER_BLOCK];
        float accr = 0.0f;
        for (int i = threadIdx.x; i < NUM_BLOCKS; i += THREADS_PER_BLOCK)
            accr += g_partial[i];
        s_red[threadIdx.x] = accr;
        __syncthreads();
#pragma unroll
        for (int stride = THREADS_PER_BLOCK / 2; stride > 0; stride >>= 1) {
            if (threadIdx.x < stride) s_red[threadIdx.x] += s_red[threadIdx.x + stride];
            __syncthreads();
        }
        if (threadIdx.x == 0) {
            out[0] = s_red[0] * (1.0f / (float)B_ROWS);
            __threadfence();
            g_count = 0;   // reset for next graph replay
        }
    }
}

extern "C" void kernel_launch(void* const* d_in, const int* in_sizes, int n_in,
                              void* d_out, int out_size)
{
    const float* input   = (const float*)d_in[0];
    const float* factor  = (const float*)d_in[1];
    const int*   label   = (const int*)d_in[2];
    const float* centers = (const float*)d_in[3];
    float* out = (float*)d_out;

    predict_kernel<<<NUM_BLOCKS, THREADS_PER_BLOCK>>>(input, factor, label, centers, out, out_size);
}